// round 16
// baseline (speedup 1.0000x reference)
#include <cuda_runtime.h>
#include <cstdint>

// Problem constants (fixed by the dataset)
#define BB 32
#define LL 1024
#define HH 384
#define ROW_BYTES (HH * 4)   // 1536 B per row
#define H4 (HH / 4)          // 96 float4 per row
#define MAX_DUR 8
#define T_MAX (LL * (MAX_DUR - 1))   // 7168
#define RPT 8
#define TILE_T 32
#define TILE_BYTES (TILE_T * ROW_BYTES)  // 48 KB

// Scratch (no cudaMalloc allowed)
__device__ __align__(16) int g_idx[BB * T_MAX];
__device__ int g_total[BB];

// ---------------------------------------------------------------------------
// Kernel 1: per-batch scan + SMEM-staged scatter + coalesced copy (R15).
// ---------------------------------------------------------------------------
__global__ void lr_scan_scatter_kernel(const int* __restrict__ dur, int T) {
    __shared__ __align__(16) int s_idx[T_MAX];
    __shared__ int wsum[32];

    const int b = blockIdx.x;
    const int tid = threadIdx.x;            // 0..1023
    const int lane = tid & 31;
    const int wid = tid >> 5;

    const int d = dur[b * LL + tid];
    int x = d;

    #pragma unroll
    for (int o = 1; o < 32; o <<= 1) {
        int y = __shfl_up_sync(0xFFFFFFFFu, x, o);
        if (lane >= o) x += y;
    }
    if (lane == 31) wsum[wid] = x;
    __syncthreads();
    if (wid == 0) {
        int s = wsum[lane];
        #pragma unroll
        for (int o = 1; o < 32; o <<= 1) {
            int y = __shfl_up_sync(0xFFFFFFFFu, s, o);
            if (lane >= o) s += y;
        }
        wsum[lane] = s;
    }
    __syncthreads();
    if (wid > 0) x += wsum[wid - 1];

    const int start = x - d;
    #pragma unroll
    for (int k = 0; k < MAX_DUR; k++) {
        if (k < d) s_idx[start + k] = tid;
    }
    if (tid == LL - 1) g_total[b] = x;
    __syncthreads();

    const int n4 = (T + TILE_T - 1) / TILE_T * (TILE_T / 4);
    int4* __restrict__ dst = (int4*)(g_idx + b * T_MAX);
    const int4* __restrict__ srcv = (const int4*)s_idx;
    for (int i = tid; i < n4; i += LL) dst[i] = srcv[i];
}

// ---------------------------------------------------------------------------
// Kernel 2: expand via async staging.
//  - gathers: cp.async.cg 16B GMEM->SMEM (zero-fill for dead rows)
//  - store:   one cp.async.bulk 48KB SMEM->GMEM per tile (contiguous)
// Block (96,4); 48KB dynamic SMEM; 4 blocks/SM.
// ---------------------------------------------------------------------------
__global__ void __launch_bounds__(384, 4)
lr_expand_kernel(const float* __restrict__ hid,
                 float* __restrict__ out,
                 float* __restrict__ mask,
                 int T) {
    extern __shared__ __align__(16) char smem[];
    const int lane = threadIdx.x;           // 0..95
    const int ty = threadIdx.y;             // 0..3
    const int tl = ty * H4 + lane;          // 0..383
    const int b = blockIdx.y;
    const int tile0 = blockIdx.x * TILE_T;
    const int t0 = tile0 + ty * RPT;

    const int total = g_total[b];

    // per-y-warp source indices (aligned int4 pairs; stride T_MAX)
    const int* __restrict__ idx_row = g_idx + b * T_MAX;
    int idx[RPT];
    *(int4*)(&idx[0]) = *(const int4*)(idx_row + t0);
    *(int4*)(&idx[4]) = *(const int4*)(idx_row + t0 + 4);

    uint32_t sbase;
    asm("{ .reg .u64 t; cvta.to.shared.u64 t, %1; cvt.u32.u64 %0, t; }"
        : "=r"(sbase) : "l"(smem));
    sbase += (uint32_t)(ty * RPT * ROW_BYTES + lane * 16);

    const char* __restrict__ srcb =
        (const char*)hid + (size_t)b * LL * ROW_BYTES + (size_t)lane * 16;

    #pragma unroll
    for (int k = 0; k < RPT; k++) {
        const bool live = (t0 + k < total);
        const int ik = live ? idx[k] : 0;           // valid address always
        const char* gsrc = srcb + (size_t)ik * ROW_BYTES;
        const int sz = live ? 16 : 0;               // 0 => zero-fill 16B
        asm volatile("cp.async.cg.shared.global [%0], [%1], 16, %2;\n"
                     :: "r"(sbase + (uint32_t)(k * ROW_BYTES)), "l"(gsrc), "r"(sz));
    }
    asm volatile("cp.async.commit_group;\n");
    asm volatile("cp.async.wait_group 0;\n" ::: "memory");
    __syncthreads();

    const int rows = (T - tile0 < TILE_T) ? (T - tile0) : TILE_T;

    // mask: 32 coalesced scalar stores
    if (tl < rows)
        mask[(size_t)b * T + tile0 + tl] = (tile0 + tl < total) ? 1.f : 0.f;

    // bulk store of the contiguous output tile
    asm volatile("fence.proxy.async.shared::cta;\n" ::: "memory");
    if (tl == 0) {
        uint32_t s0;
        asm("{ .reg .u64 t; cvta.to.shared.u64 t, %1; cvt.u32.u64 %0, t; }"
            : "=r"(s0) : "l"(smem));
        char* gdst = (char*)out + ((size_t)b * T + tile0) * ROW_BYTES;
        const uint32_t bytes = (uint32_t)rows * ROW_BYTES;
        asm volatile("cp.async.bulk.global.shared::cta.bulk_group [%0], [%1], %2;\n"
                     :: "l"(gdst), "r"(s0), "r"(bytes) : "memory");
        asm volatile("cp.async.bulk.commit_group;\n");
        asm volatile("cp.async.bulk.wait_group 0;\n" ::: "memory");
    }
}

// ---------------------------------------------------------------------------
extern "C" void kernel_launch(void* const* d_in, const int* in_sizes, int n_in,
                              void* d_out, int out_size) {
    const float* hid = (const float*)d_in[0];   // (B, L, H) f32
    const int*   dur = (const int*)d_in[1];     // (B, L) i32

    const int T = out_size / (BB * (HH + 1));
    const long long n_rows = (long long)BB * T;

    float* out  = (float*)d_out;                // B*T*H
    float* mask = (float*)d_out + n_rows * HH;  // B*T

    lr_scan_scatter_kernel<<<BB, LL>>>(dur, T);

    static bool attr_set = false;
    if (!attr_set) {
        cudaFuncSetAttribute(lr_expand_kernel,
                             cudaFuncAttributeMaxDynamicSharedMemorySize,
                             TILE_BYTES);
        attr_set = true;
    }

    dim3 grid((T + TILE_T - 1) / TILE_T, BB);
    dim3 blk(H4, 4);
    lr_expand_kernel<<<grid, blk, TILE_BYTES>>>(hid, out, mask, T);
}

// round 17
// speedup vs baseline: 1.0375x; 1.0375x over previous
#include <cuda_runtime.h>

// Problem constants (fixed by the dataset)
#define BB 32
#define LL 1024
#define HH 384
#define H4 (HH / 4)          // 96 float4 per row
#define MAX_DUR 8
#define T_MAX (LL * (MAX_DUR - 1))   // 7168, multiple of 4 -> int4-aligned rows
#define RPT 8                // rows per thread
#define TILE_T 32            // rows per block (4 y-slices * 8)
#define SCAN_THREADS 256     // 4 durations per thread

// Scratch (no cudaMalloc allowed). Row stride is T_MAX so every int4 idx
// load is aligned regardless of runtime T.
__device__ __align__(16) int g_idx[BB * T_MAX];
__device__ int g_total[BB];

// ---------------------------------------------------------------------------
// Kernel 1: lean per-batch scan. 256 threads x 4 durations (one int4 each):
// serial 4-sum + warp scan + 8-warp combine, SMEM-staged scatter, coalesced
// int4 copy to g_idx. Early PDL trigger releases the dependent expand grid.
// ---------------------------------------------------------------------------
__global__ void lr_scan_scatter_kernel(const int* __restrict__ dur, int T) {
    __shared__ __align__(16) int s_idx[T_MAX];   // 28 KB
    __shared__ int wsum[8];

    const int b = blockIdx.x;
    const int tid = threadIdx.x;            // 0..255
    const int lane = tid & 31;
    const int wid = tid >> 5;               // 0..7

    const int4 dv = *(const int4*)(dur + b * LL + tid * 4);
    const int sum = dv.x + dv.y + dv.z + dv.w;

    int x = sum;
    #pragma unroll
    for (int o = 1; o < 32; o <<= 1) {
        int y = __shfl_up_sync(0xFFFFFFFFu, x, o);
        if (lane >= o) x += y;
    }
    if (lane == 31) wsum[wid] = x;
    __syncthreads();

    int base = 0;
    #pragma unroll
    for (int w = 0; w < 7; w++)
        if (wid > w) base += wsum[w];

    // exclusive prefix before this thread's 4 elements
    int run = base + x - sum;

    // scatter into SMEM: each of my 4 elements j covers frames [run, run+d_j)
    {
        int d0 = dv.x, d1 = dv.y, d2 = dv.z, d3 = dv.w;
        const int j0 = tid * 4;
        int e;
        e = run + d0; for (int t = run; t < e; t++) s_idx[t] = j0;     run = e;
        e = run + d1; for (int t = run; t < e; t++) s_idx[t] = j0 + 1; run = e;
        e = run + d2; for (int t = run; t < e; t++) s_idx[t] = j0 + 2; run = e;
        e = run + d3; for (int t = run; t < e; t++) s_idx[t] = j0 + 3; run = e;
    }
    if (tid == SCAN_THREADS - 1) g_total[b] = run;
    __syncthreads();

    // coalesced copy SMEM -> global (int4); covers all tiles expand reads
    const int n4 = (T + TILE_T - 1) / TILE_T * (TILE_T / 4);  // tile-padded
    int4* __restrict__ dst = (int4*)(g_idx + b * T_MAX);
    const int4* __restrict__ srcv = (const int4*)s_idx;
    for (int i = tid; i < n4; i += SCAN_THREADS) dst[i] = srcv[i];

    // Release the dependent expand grid as soon as this block is done.
    cudaTriggerProgrammaticLaunchCompletion();
}

// ---------------------------------------------------------------------------
// Kernel 2: expand (champion config, unchanged). 8 contiguous rows per
// thread, front-batched gathers with duplicate-source dedup, streaming
// stores. PDL: independent setup before cudaGridDependencySynchronize().
// ---------------------------------------------------------------------------
__global__ void __launch_bounds__(384, 3)
lr_expand_kernel(const float* __restrict__ hid,
                 float* __restrict__ out,
                 float* __restrict__ mask,
                 int T) {
    const int lane = threadIdx.x;           // 0..95
    const int b = blockIdx.y;
    const int t0 = blockIdx.x * TILE_T + threadIdx.y * RPT;

    // Independent setup (overlaps the scan under PDL)
    const int* __restrict__ idx_row = g_idx + b * T_MAX;
    const float4* __restrict__ src =
        (const float4*)(hid) + (long long)b * LL * H4 + lane;
    float4* __restrict__ dst =
        (float4*)(out) + ((long long)b * T + t0) * H4 + lane;
    const float4 z = make_float4(0.f, 0.f, 0.f, 0.f);
    const bool in_range = (t0 < T);
    const bool full = (t0 + RPT <= T);

    cudaGridDependencySynchronize();

    if (!in_range) return;
    const int total = g_total[b];

    // idx loads: always in-bounds and 16B-aligned (stride T_MAX, t0 % 8 == 0)
    int idx[RPT];
    *(int4*)(&idx[0]) = *(const int4*)(idx_row + t0);
    *(int4*)(&idx[4]) = *(const int4*)(idx_row + t0 + 4);

    // Front-batched gathers, skipping duplicates of the previous row.
    float4 v[RPT];
    #pragma unroll
    for (int k = 0; k < RPT; k++) {
        float4 vv = z;
        const bool live = (t0 + k < total);
        const bool dup = (k > 0) && (idx[k] == idx[k - 1]);
        if (live && !dup) vv = src[idx[k] * H4];
        v[k] = vv;
    }
    // Propagate duplicates (sequential, handles chains).
    #pragma unroll
    for (int k = 1; k < RPT; k++) {
        if ((t0 + k < total) && (idx[k] == idx[k - 1])) v[k] = v[k - 1];
    }

    if (full) {
        #pragma unroll
        for (int k = 0; k < RPT; k++) __stcs(dst + k * H4, v[k]);

        if (lane == 0) {
            float4 m0, m1;
            m0.x = (t0 + 0 < total) ? 1.f : 0.f;
            m0.y = (t0 + 1 < total) ? 1.f : 0.f;
            m0.z = (t0 + 2 < total) ? 1.f : 0.f;
            m0.w = (t0 + 3 < total) ? 1.f : 0.f;
            m1.x = (t0 + 4 < total) ? 1.f : 0.f;
            m1.y = (t0 + 5 < total) ? 1.f : 0.f;
            m1.z = (t0 + 6 < total) ? 1.f : 0.f;
            m1.w = (t0 + 7 < total) ? 1.f : 0.f;
            float4* mp = (float4*)(mask + (long long)b * T + t0);
            __stcs(mp, m0);
            __stcs(mp + 1, m1);
        }
    } else {
        // T-tail: per-row bounds
        #pragma unroll
        for (int k = 0; k < RPT; k++) {
            if (t0 + k < T) {
                __stcs(dst + k * H4, v[k]);
                if (lane == 0)
                    mask[(long long)b * T + t0 + k] = (t0 + k < total) ? 1.f : 0.f;
            }
        }
    }
}

// ---------------------------------------------------------------------------
extern "C" void kernel_launch(void* const* d_in, const int* in_sizes, int n_in,
                              void* d_out, int out_size) {
    const float* hid = (const float*)d_in[0];   // (B, L, H) f32
    const int*   dur = (const int*)d_in[1];     // (B, L) i32

    // out_size = B*T*H + B*T = B*T*(H+1)
    const int T = out_size / (BB * (HH + 1));
    const long long n_rows = (long long)BB * T;

    float* out  = (float*)d_out;                // B*T*H
    float* mask = (float*)d_out + n_rows * HH;  // B*T

    lr_scan_scatter_kernel<<<BB, SCAN_THREADS>>>(dur, T);

    // Expand with programmatic dependent launch: launch/setup overlaps the
    // scan; dependent reads fenced by cudaGridDependencySynchronize.
    cudaLaunchConfig_t cfg = {};
    cfg.gridDim = dim3((T + TILE_T - 1) / TILE_T, BB);
    cfg.blockDim = dim3(H4, 4);
    cfg.dynamicSmemBytes = 0;
    cfg.stream = 0;
    cudaLaunchAttribute attr[1];
    attr[0].id = cudaLaunchAttributeProgrammaticStreamSerialization;
    attr[0].val.programmaticStreamSerializationAllowed = 1;
    cfg.attrs = attr;
    cfg.numAttrs = 1;
    cudaLaunchKernelEx(&cfg, lr_expand_kernel, hid, out, mask, T);
}